// round 7
// baseline (speedup 1.0000x reference)
#include <cuda_runtime.h>
#include <math.h>

#define POI   5000
#define EMB   256
#define UNITS 512
#define QDIM  256
#define BATCH 64
#define X1DIM  (EMB + QDIM)        // 512
#define CATDIM (EMB + 2 * UNITS)   // 1280
#define NCH    10                  // context p-chunks (5000/10 = 500)

// ---------------- scratch (no cudaMalloc allowed) ----------------
__device__ float g_h[BATCH * UNITS];
__device__ float g_qproj[BATCH * UNITS];
__device__ float g_vproj[POI * UNITS];            // 10.24 MB
__device__ float g_score[BATCH * POI];
__device__ float g_ctxpart[NCH * BATCH * EMB];
__device__ float g_outcat[BATCH * CATDIM];
__device__ float g_part[10 * BATCH * POI];        // partial slabs (12.8 MB max: fc S=10)

__device__ __forceinline__ float tanh_ap(float x) {
    float y;
    asm("tanh.approx.f32 %0, %1;" : "=f"(y) : "f"(x));
    return y;
}

// ---------------- gemm_v2: C[M,N] = A[M,K] @ W[K,N] (+bias iff gridDim.z==1) -----
template <int BM, int BN, int TM, int TN>
__global__ void gemm_v2_kernel(const float* __restrict__ A,
                               const float* __restrict__ W,
                               const float* __restrict__ bias,
                               float* __restrict__ out,
                               int M, int N, int K, int kchunk) {
    __shared__ float As[32][BM + 1];   // As[k][m]
    __shared__ float Ws[32][BN];       // Ws[k][n]
    const int tid = threadIdx.x;
    const int r = tid >> 4;
    const int c = tid & 15;
    const int n0 = blockIdx.x * BN;
    const int m0 = blockIdx.y * BM;
    const int kbase = blockIdx.z * kchunk;

    float acc[TM][TN];
#pragma unroll
    for (int i = 0; i < TM; i++)
#pragma unroll
        for (int j = 0; j < TN; j++) acc[i][j] = 0.f;

    for (int kk = kbase; kk < kbase + kchunk; kk += 32) {
#pragma unroll
        for (int pass = 0; pass < (BM * 32) / 1024; pass++) {
            int idx = pass * 1024 + tid * 4;
            int m = idx >> 5;
            int k = idx & 31;
            float4 v = make_float4(0.f, 0.f, 0.f, 0.f);
            if (m0 + m < M) v = *(const float4*)(A + (size_t)(m0 + m) * K + kk + k);
            As[k + 0][m] = v.x;
            As[k + 1][m] = v.y;
            As[k + 2][m] = v.z;
            As[k + 3][m] = v.w;
        }
#pragma unroll
        for (int pass = 0; pass < (32 * BN) / 1024; pass++) {
            int idx = pass * 1024 + tid * 4;
            int k = idx / BN;
            int n = idx % BN;
            float4 v = make_float4(0.f, 0.f, 0.f, 0.f);
            if (n0 + n < N) v = *(const float4*)(W + (size_t)(kk + k) * N + n0 + n);
            *(float4*)&Ws[k][n] = v;
        }
        __syncthreads();
#pragma unroll
        for (int k = 0; k < 32; k++) {
            float a[TM];
#pragma unroll
            for (int i = 0; i < TM; i++) a[i] = As[k][r * TM + i];
            float b[TN];
#pragma unroll
            for (int j = 0; j < TN; j += 4)
                *(float4*)&b[j] = *(const float4*)&Ws[k][c * TN + j];
#pragma unroll
            for (int i = 0; i < TM; i++)
#pragma unroll
                for (int j = 0; j < TN; j++)
                    acc[i][j] = fmaf(a[i], b[j], acc[i][j]);
        }
        __syncthreads();
    }

    const bool direct = (gridDim.z == 1);
    float* dst = direct ? out : out + (size_t)blockIdx.z * M * N;
#pragma unroll
    for (int i = 0; i < TM; i++) {
        int m = m0 + r * TM + i;
        if (m >= M) continue;
#pragma unroll
        for (int j = 0; j < TN; j += 4) {
            int n = n0 + c * TN + j;
            if (n < N) {
                float4 v;
                v.x = acc[i][j + 0] + (direct ? bias[n + 0] : 0.f);
                v.y = acc[i][j + 1] + (direct ? bias[n + 1] : 0.f);
                v.z = acc[i][j + 2] + (direct ? bias[n + 2] : 0.f);
                v.w = acc[i][j + 3] + (direct ? bias[n + 3] : 0.f);
                *(float4*)(dst + (size_t)m * N + n) = v;
            }
        }
    }
}

// ---------------- merged GRU matmuls: slabs 0..7 = xm (x1 built inline), 8..15 = hm
__global__ void gru_mm_kernel(const int* __restrict__ x,
                              const float* __restrict__ query,
                              const float* __restrict__ emb,
                              const float* __restrict__ dec_hidden,
                              const float* __restrict__ Wk,
                              const float* __restrict__ Wr,
                              float* __restrict__ part) {
    const int NN = 3 * UNITS;
    __shared__ float As[32][65];
    __shared__ float Ws[32][64];
    const int tid = threadIdx.x;
    const int r = tid >> 4;
    const int c = tid & 15;
    const int n0 = blockIdx.x * 64;
    const bool isX = blockIdx.z < 8;
    const int kbase = (isX ? blockIdx.z : blockIdx.z - 8) * 64;
    const float* W = isX ? Wk : Wr;

    float acc[4][4];
#pragma unroll
    for (int i = 0; i < 4; i++)
#pragma unroll
        for (int j = 0; j < 4; j++) acc[i][j] = 0.f;

    for (int kk = kbase; kk < kbase + 64; kk += 32) {
#pragma unroll
        for (int pass = 0; pass < 2; pass++) {
            int idx = pass * 1024 + tid * 4;
            int m = idx >> 5;
            int k = idx & 31;
            int gk = kk + k;
            float4 v;
            if (isX) {
                if (gk < EMB)
                    v = *(const float4*)(emb + (size_t)x[m] * EMB + gk);
                else
                    v = *(const float4*)(query + (size_t)m * QDIM + gk - EMB);
            } else {
                v = *(const float4*)(dec_hidden + (size_t)m * UNITS + gk);
            }
            As[k + 0][m] = v.x;
            As[k + 1][m] = v.y;
            As[k + 2][m] = v.z;
            As[k + 3][m] = v.w;
        }
#pragma unroll
        for (int pass = 0; pass < 2; pass++) {
            int idx = pass * 1024 + tid * 4;
            int k = idx >> 6;
            int n = idx & 63;
            *(float4*)&Ws[k][n] = *(const float4*)(W + (size_t)(kk + k) * NN + n0 + n);
        }
        __syncthreads();
#pragma unroll
        for (int k = 0; k < 32; k++) {
            float a0 = As[k][r * 4 + 0];
            float a1 = As[k][r * 4 + 1];
            float a2 = As[k][r * 4 + 2];
            float a3 = As[k][r * 4 + 3];
            float4 b = *(const float4*)&Ws[k][c * 4];
            acc[0][0] = fmaf(a0, b.x, acc[0][0]); acc[0][1] = fmaf(a0, b.y, acc[0][1]);
            acc[0][2] = fmaf(a0, b.z, acc[0][2]); acc[0][3] = fmaf(a0, b.w, acc[0][3]);
            acc[1][0] = fmaf(a1, b.x, acc[1][0]); acc[1][1] = fmaf(a1, b.y, acc[1][1]);
            acc[1][2] = fmaf(a1, b.z, acc[1][2]); acc[1][3] = fmaf(a1, b.w, acc[1][3]);
            acc[2][0] = fmaf(a2, b.x, acc[2][0]); acc[2][1] = fmaf(a2, b.y, acc[2][1]);
            acc[2][2] = fmaf(a2, b.z, acc[2][2]); acc[2][3] = fmaf(a2, b.w, acc[2][3]);
            acc[3][0] = fmaf(a3, b.x, acc[3][0]); acc[3][1] = fmaf(a3, b.y, acc[3][1]);
            acc[3][2] = fmaf(a3, b.z, acc[3][2]); acc[3][3] = fmaf(a3, b.w, acc[3][3]);
        }
        __syncthreads();
    }

    float* dst = part + (size_t)blockIdx.z * BATCH * NN;
#pragma unroll
    for (int i = 0; i < 4; i++) {
        int m = r * 4 + i;
        int n = n0 + c * 4;
        float4 v = make_float4(acc[i][0], acc[i][1], acc[i][2], acc[i][3]);
        *(float4*)(dst + (size_t)m * NN + n) = v;
    }
}

// ---------------- reduce K-split partials + bias ----------------
__global__ void reduce_bias_kernel(const float* __restrict__ part,
                                   const float* __restrict__ bias,
                                   float* __restrict__ C,
                                   int MN, int N, int S) {
    int i = blockIdx.x * 256 + threadIdx.x;
    if (i >= MN) return;
    float s = 0.f;
    for (int z = 0; z < S; z++) s += part[(size_t)z * MN + i];
    C[i] = s + bias[i % N];
}

// ---------------- GRU gates: sums 8 xm slabs + 8 hm slabs + bias ----------------
__global__ void gru_gates_kernel(const float* __restrict__ part,
                                 const float* __restrict__ bias,
                                 const float* __restrict__ h_in,
                                 float* __restrict__ h_scratch,
                                 float* __restrict__ out_state,
                                 float* __restrict__ out_output) {
    const int NN = 3 * UNITS;
    int b = blockIdx.x;
    int u = threadIdx.x;               // 512
    float xz = bias[u], xr = bias[UNITS + u], xh = bias[2 * UNITS + u];
    float hz = bias[NN + u], hr = bias[NN + UNITS + u], hh = bias[NN + 2 * UNITS + u];
#pragma unroll
    for (int z = 0; z < 8; z++) {
        const float* px = part + (size_t)z * BATCH * NN + b * NN;
        const float* ph = part + (size_t)(8 + z) * BATCH * NN + b * NN;
        xz += px[u]; xr += px[UNITS + u]; xh += px[2 * UNITS + u];
        hz += ph[u]; hr += ph[UNITS + u]; hh += ph[2 * UNITS + u];
    }
    float z = 1.f / (1.f + expf(-(xz + hz)));
    float r = 1.f / (1.f + expf(-(xr + hr)));
    float hc = tanhf(xh + r * hh);
    float h = h_in[b * UNITS + u];
    float hn = z * h + (1.f - z) * hc;
    h_scratch[b * UNITS + u] = hn;
    if (out_state)  out_state[b * UNITS + u] = hn;
    if (out_output) out_output[b * UNITS + u] = hn;
}

// ---------------- attention score, 8 batch rows per block ----------------
// grid (ceil(POI/128), BATCH/8), block 128.
__global__ void attn_score_kernel(const float* __restrict__ vproj,
                                  const float* __restrict__ qproj,
                                  const float* __restrict__ Vw,
                                  const float* __restrict__ Vb,
                                  float* __restrict__ score) {
    __shared__ float q_s[8][UNITS];    // 16 KB
    __shared__ float vw_s[UNITS];      // 2 KB
    __shared__ float v_s[128][33];     // 16.9 KB
    const int tid = threadIdx.x;       // 128
    const int p0 = blockIdx.x * 128;
    const int b0 = blockIdx.y * 8;

    for (int t = tid; t < 8 * UNITS; t += 128) {
        int b = t >> 9, u = t & 511;
        q_s[b][u] = qproj[(b0 + b) * UNITS + u];
    }
    for (int t = tid; t < UNITS; t += 128) vw_s[t] = Vw[t];

    float acc[8];
#pragma unroll
    for (int b = 0; b < 8; b++) acc[b] = 0.f;

    for (int u0 = 0; u0 < UNITS; u0 += 32) {
        __syncthreads();               // also covers q_s/vw_s on first iter
        for (int t = tid; t < 128 * 32; t += 128) {
            int p = t >> 5, j = t & 31;
            v_s[p][j] = (p0 + p < POI) ? vproj[(p0 + p) * UNITS + u0 + j] : 0.f;
        }
        __syncthreads();
#pragma unroll
        for (int j = 0; j < 32; ++j) {
            float v  = v_s[tid][j];
            float vw = vw_s[u0 + j];
#pragma unroll
            for (int b = 0; b < 8; b++)
                acc[b] = fmaf(vw, tanh_ap(v + q_s[b][u0 + j]), acc[b]);
        }
    }
    if (p0 + tid < POI) {
        float vb = Vb[0];
#pragma unroll
        for (int b = 0; b < 8; b++)
            score[(b0 + b) * POI + p0 + tid] = acc[b] + vb;
    }
}

// ---------------- softmax over POI per batch row (in place) ----------------
__global__ void softmax_rows_kernel(float* __restrict__ score) {
    int b = blockIdx.x;
    int tid = threadIdx.x;             // 256
    __shared__ float red[256];
    float m = -1e30f;
    for (int p = tid; p < POI; p += 256) m = fmaxf(m, score[b * POI + p]);
    red[tid] = m;
    __syncthreads();
    for (int s = 128; s > 0; s >>= 1) {
        if (tid < s) red[tid] = fmaxf(red[tid], red[tid + s]);
        __syncthreads();
    }
    m = red[0];
    __syncthreads();
    float sum = 0.f;
    for (int p = tid; p < POI; p += 256) {
        float e = __expf(score[b * POI + p] - m);
        score[b * POI + p] = e;
        sum += e;
    }
    red[tid] = sum;
    __syncthreads();
    for (int s = 128; s > 0; s >>= 1) {
        if (tid < s) red[tid] += red[tid + s];
        __syncthreads();
    }
    float inv = 1.f / red[0];
    for (int p = tid; p < POI; p += 256) score[b * POI + p] *= inv;
}

// ---------------- context partials: 8 batch rows per block, NCH p-chunks --------
__global__ void context_partial_kernel(const float* __restrict__ attn,
                                       const float* __restrict__ emb,
                                       float* __restrict__ part) {
    const int PC = POI / NCH;          // 500
    int b0 = blockIdx.x * 8;
    int ch = blockIdx.y;
    int e  = threadIdx.x;              // 256 == EMB
    int p0 = ch * PC;
    float acc[8];
#pragma unroll
    for (int b = 0; b < 8; b++) acc[b] = 0.f;
#pragma unroll 2
    for (int p = p0; p < p0 + PC; ++p) {
        float ev = emb[p * EMB + e];
#pragma unroll
        for (int b = 0; b < 8; b++)
            acc[b] = fmaf(attn[(b0 + b) * POI + p], ev, acc[b]);
    }
#pragma unroll
    for (int b = 0; b < 8; b++)
        part[(ch * BATCH + b0 + b) * EMB + e] = acc[b];
}

// ---------------- outcat = [sum(ctx partials) | h | cat_dec] ----------------
__global__ void build_outcat_kernel(const float* __restrict__ part,
                                    const float* __restrict__ h,
                                    const float* __restrict__ cat_dec,
                                    float* __restrict__ outcat) {
    int b = blockIdx.x;
    int e = threadIdx.x;               // 256
    float s = 0.f;
#pragma unroll
    for (int ch = 0; ch < NCH; ch++) s += part[(ch * BATCH + b) * EMB + e];
    outcat[b * CATDIM + e] = s;
    for (int c = e; c < UNITS; c += 256) {
        outcat[b * CATDIM + EMB + c]         = h[b * UNITS + c];
        outcat[b * CATDIM + EMB + UNITS + c] = cat_dec[b * UNITS + c];
    }
}

// ---------------- launch ----------------
extern "C" void kernel_launch(void* const* d_in, const int* in_sizes, int n_in,
                              void* d_out, int out_size) {
    const int*   x          = (const int*)  d_in[0];
    const float* query      = (const float*)d_in[1];
    const float* emb        = (const float*)d_in[2];
    // d_in[3] = A_hat (unused)
    const float* dec_hidden = (const float*)d_in[4];
    const float* cat_dec    = (const float*)d_in[5];
    const float* gru_kernel = (const float*)d_in[6];
    const float* gru_rec    = (const float*)d_in[7];
    const float* gru_bias   = (const float*)d_in[8];
    const float* W1_w       = (const float*)d_in[9];
    const float* W1_b       = (const float*)d_in[10];
    const float* W2_w       = (const float*)d_in[11];
    const float* W2_b       = (const float*)d_in[12];
    const float* V_w        = (const float*)d_in[13];
    const float* V_b        = (const float*)d_in[14];
    const float* fc_w       = (const float*)d_in[15];
    const float* fc_b       = (const float*)d_in[16];

    float* out        = (float*)d_out;
    float* out_logits = out;
    float* out_state  = (out_size >= BATCH * POI + BATCH * UNITS)
                        ? out + BATCH * POI : nullptr;
    float* out_output = (out_size >= BATCH * POI + 2 * BATCH * UNITS)
                        ? out + BATCH * POI + BATCH * UNITS : nullptr;

    float *g_h_p, *g_qp_p, *g_vp_p, *g_sc_p, *g_cp_p, *g_oc_p, *g_pt_p;
    cudaGetSymbolAddress((void**)&g_h_p,  g_h);
    cudaGetSymbolAddress((void**)&g_qp_p, g_qproj);
    cudaGetSymbolAddress((void**)&g_vp_p, g_vproj);
    cudaGetSymbolAddress((void**)&g_sc_p, g_score);
    cudaGetSymbolAddress((void**)&g_cp_p, g_ctxpart);
    cudaGetSymbolAddress((void**)&g_oc_p, g_outcat);
    cudaGetSymbolAddress((void**)&g_pt_p, g_part);

    // (1) GRU merged matmuls, (2) gates
    gru_mm_kernel<<<dim3(3 * UNITS / 64, 1, 16), 256>>>(
        x, query, emb, dec_hidden, gru_kernel, gru_rec, g_pt_p);
    gru_gates_kernel<<<BATCH, UNITS>>>(g_pt_p, gru_bias, dec_hidden,
                                       g_h_p, out_state, out_output);

    // (3) q_proj gemm (split 8)
    gemm_v2_kernel<64, 64, 4, 4><<<dim3(UNITS / 64, 1, 8), 256>>>(
        g_h_p, W2_w, nullptr, g_pt_p, BATCH, UNITS, UNITS, 64);

    // (4) v_proj = emb @ W1 + b : 64x64 tiles, 632 CTAs (profiled launch)
    gemm_v2_kernel<64, 64, 4, 4><<<dim3(UNITS / 64, (POI + 63) / 64, 1), 256>>>(
        emb, W1_w, W1_b, g_vp_p, POI, UNITS, EMB, EMB);

    // (5) q_proj reduce
    reduce_bias_kernel<<<(BATCH * UNITS + 255) / 256, 256>>>(
        g_pt_p, W2_b, g_qp_p, BATCH * UNITS, UNITS, 8);

    // (6) attention score, (7) softmax, (8) context, (9) outcat
    attn_score_kernel<<<dim3((POI + 127) / 128, BATCH / 8), 128>>>(
        g_vp_p, g_qp_p, V_w, V_b, g_sc_p);
    softmax_rows_kernel<<<BATCH, 256>>>(g_sc_p);
    context_partial_kernel<<<dim3(BATCH / 8, NCH), 256>>>(g_sc_p, emb, g_cp_p);
    build_outcat_kernel<<<BATCH, 256>>>(g_cp_p, g_h_p, cat_dec, g_oc_p);

    // (10) logits gemm (split 10), (11) reduce
    gemm_v2_kernel<64, 128, 4, 8><<<dim3((POI + 127) / 128, 1, 10), 256>>>(
        g_oc_p, fc_w, nullptr, g_pt_p, BATCH, POI, CATDIM, 128);
    reduce_bias_kernel<<<(BATCH * POI + 255) / 256, 256>>>(
        g_pt_p, fc_b, out_logits, BATCH * POI, POI, 10);
}

// round 8
// speedup vs baseline: 1.3069x; 1.3069x over previous
#include <cuda_runtime.h>
#include <math.h>

#define POI   5000
#define EMB   256
#define UNITS 512
#define QDIM  256
#define BATCH 64
#define X1DIM  (EMB + QDIM)        // 512
#define CATDIM (EMB + 2 * UNITS)   // 1280
#define NCH    10                  // context p-chunks (5000/10 = 500)

// ---------------- scratch (no cudaMalloc allowed) ----------------
__device__ float g_h[BATCH * UNITS];
__device__ float g_qproj[BATCH * UNITS];
__device__ float g_vproj[POI * UNITS];            // 10.24 MB
__device__ float g_score[BATCH * POI];
__device__ float g_ctxpart[NCH * BATCH * EMB];
__device__ float g_outcat[BATCH * CATDIM];
__device__ float g_part[10 * BATCH * POI];        // partial slabs (12.8 MB max: fc S=10)

__device__ __forceinline__ float tanh_ap(float x) {
    float y;
    asm("tanh.approx.f32 %0, %1;" : "=f"(y) : "f"(x));
    return y;
}

// ---------------- gemm_v2: C[M,N] = A[M,K] @ W[K,N] (+bias iff gridDim.z==1) -----
template <int BM, int BN, int TM, int TN>
__global__ void gemm_v2_kernel(const float* __restrict__ A,
                               const float* __restrict__ W,
                               const float* __restrict__ bias,
                               float* __restrict__ out,
                               int M, int N, int K, int kchunk) {
    __shared__ float As[32][BM + 1];   // As[k][m]
    __shared__ float Ws[32][BN];       // Ws[k][n]
    const int tid = threadIdx.x;
    const int r = tid >> 4;
    const int c = tid & 15;
    const int n0 = blockIdx.x * BN;
    const int m0 = blockIdx.y * BM;
    const int kbase = blockIdx.z * kchunk;

    float acc[TM][TN];
#pragma unroll
    for (int i = 0; i < TM; i++)
#pragma unroll
        for (int j = 0; j < TN; j++) acc[i][j] = 0.f;

    for (int kk = kbase; kk < kbase + kchunk; kk += 32) {
#pragma unroll
        for (int pass = 0; pass < (BM * 32) / 1024; pass++) {
            int idx = pass * 1024 + tid * 4;
            int m = idx >> 5;
            int k = idx & 31;
            float4 v = make_float4(0.f, 0.f, 0.f, 0.f);
            if (m0 + m < M) v = *(const float4*)(A + (size_t)(m0 + m) * K + kk + k);
            As[k + 0][m] = v.x;
            As[k + 1][m] = v.y;
            As[k + 2][m] = v.z;
            As[k + 3][m] = v.w;
        }
#pragma unroll
        for (int pass = 0; pass < (32 * BN) / 1024; pass++) {
            int idx = pass * 1024 + tid * 4;
            int k = idx / BN;
            int n = idx % BN;
            float4 v = make_float4(0.f, 0.f, 0.f, 0.f);
            if (n0 + n < N) v = *(const float4*)(W + (size_t)(kk + k) * N + n0 + n);
            *(float4*)&Ws[k][n] = v;
        }
        __syncthreads();
#pragma unroll
        for (int k = 0; k < 32; k++) {
            float a[TM];
#pragma unroll
            for (int i = 0; i < TM; i++) a[i] = As[k][r * TM + i];
            float b[TN];
#pragma unroll
            for (int j = 0; j < TN; j += 4)
                *(float4*)&b[j] = *(const float4*)&Ws[k][c * TN + j];
#pragma unroll
            for (int i = 0; i < TM; i++)
#pragma unroll
                for (int j = 0; j < TN; j++)
                    acc[i][j] = fmaf(a[i], b[j], acc[i][j]);
        }
        __syncthreads();
    }

    const bool direct = (gridDim.z == 1);
    float* dst = direct ? out : out + (size_t)blockIdx.z * M * N;
#pragma unroll
    for (int i = 0; i < TM; i++) {
        int m = m0 + r * TM + i;
        if (m >= M) continue;
#pragma unroll
        for (int j = 0; j < TN; j += 4) {
            int n = n0 + c * TN + j;
            if (n < N) {
                float4 v;
                v.x = acc[i][j + 0] + (direct ? bias[n + 0] : 0.f);
                v.y = acc[i][j + 1] + (direct ? bias[n + 1] : 0.f);
                v.z = acc[i][j + 2] + (direct ? bias[n + 2] : 0.f);
                v.w = acc[i][j + 3] + (direct ? bias[n + 3] : 0.f);
                *(float4*)(dst + (size_t)m * N + n) = v;
            }
        }
    }
}

// ---------------- merged GRU matmuls: slabs 0..7 = xm (x1 built inline), 8..15 = hm
__global__ void gru_mm_kernel(const int* __restrict__ x,
                              const float* __restrict__ query,
                              const float* __restrict__ emb,
                              const float* __restrict__ dec_hidden,
                              const float* __restrict__ Wk,
                              const float* __restrict__ Wr,
                              float* __restrict__ part) {
    const int NN = 3 * UNITS;
    __shared__ float As[32][65];
    __shared__ float Ws[32][64];
    const int tid = threadIdx.x;
    const int r = tid >> 4;
    const int c = tid & 15;
    const int n0 = blockIdx.x * 64;
    const bool isX = blockIdx.z < 8;
    const int kbase = (isX ? blockIdx.z : blockIdx.z - 8) * 64;
    const float* W = isX ? Wk : Wr;

    float acc[4][4];
#pragma unroll
    for (int i = 0; i < 4; i++)
#pragma unroll
        for (int j = 0; j < 4; j++) acc[i][j] = 0.f;

    for (int kk = kbase; kk < kbase + 64; kk += 32) {
#pragma unroll
        for (int pass = 0; pass < 2; pass++) {
            int idx = pass * 1024 + tid * 4;
            int m = idx >> 5;
            int k = idx & 31;
            int gk = kk + k;
            float4 v;
            if (isX) {
                if (gk < EMB)
                    v = *(const float4*)(emb + (size_t)x[m] * EMB + gk);
                else
                    v = *(const float4*)(query + (size_t)m * QDIM + gk - EMB);
            } else {
                v = *(const float4*)(dec_hidden + (size_t)m * UNITS + gk);
            }
            As[k + 0][m] = v.x;
            As[k + 1][m] = v.y;
            As[k + 2][m] = v.z;
            As[k + 3][m] = v.w;
        }
#pragma unroll
        for (int pass = 0; pass < 2; pass++) {
            int idx = pass * 1024 + tid * 4;
            int k = idx >> 6;
            int n = idx & 63;
            *(float4*)&Ws[k][n] = *(const float4*)(W + (size_t)(kk + k) * NN + n0 + n);
        }
        __syncthreads();
#pragma unroll
        for (int k = 0; k < 32; k++) {
            float a0 = As[k][r * 4 + 0];
            float a1 = As[k][r * 4 + 1];
            float a2 = As[k][r * 4 + 2];
            float a3 = As[k][r * 4 + 3];
            float4 b = *(const float4*)&Ws[k][c * 4];
            acc[0][0] = fmaf(a0, b.x, acc[0][0]); acc[0][1] = fmaf(a0, b.y, acc[0][1]);
            acc[0][2] = fmaf(a0, b.z, acc[0][2]); acc[0][3] = fmaf(a0, b.w, acc[0][3]);
            acc[1][0] = fmaf(a1, b.x, acc[1][0]); acc[1][1] = fmaf(a1, b.y, acc[1][1]);
            acc[1][2] = fmaf(a1, b.z, acc[1][2]); acc[1][3] = fmaf(a1, b.w, acc[1][3]);
            acc[2][0] = fmaf(a2, b.x, acc[2][0]); acc[2][1] = fmaf(a2, b.y, acc[2][1]);
            acc[2][2] = fmaf(a2, b.z, acc[2][2]); acc[2][3] = fmaf(a2, b.w, acc[2][3]);
            acc[3][0] = fmaf(a3, b.x, acc[3][0]); acc[3][1] = fmaf(a3, b.y, acc[3][1]);
            acc[3][2] = fmaf(a3, b.z, acc[3][2]); acc[3][3] = fmaf(a3, b.w, acc[3][3]);
        }
        __syncthreads();
    }

    float* dst = part + (size_t)blockIdx.z * BATCH * NN;
#pragma unroll
    for (int i = 0; i < 4; i++) {
        int m = r * 4 + i;
        int n = n0 + c * 4;
        float4 v = make_float4(acc[i][0], acc[i][1], acc[i][2], acc[i][3]);
        *(float4*)(dst + (size_t)m * NN + n) = v;
    }
}

// ---------------- reduce K-split partials + bias ----------------
__global__ void reduce_bias_kernel(const float* __restrict__ part,
                                   const float* __restrict__ bias,
                                   float* __restrict__ C,
                                   int MN, int N, int S) {
    int i = blockIdx.x * 256 + threadIdx.x;
    if (i >= MN) return;
    float s = 0.f;
    for (int z = 0; z < S; z++) s += part[(size_t)z * MN + i];
    C[i] = s + bias[i % N];
}

// ---------------- GRU gates: sums 8 xm slabs + 8 hm slabs + bias ----------------
__global__ void gru_gates_kernel(const float* __restrict__ part,
                                 const float* __restrict__ bias,
                                 const float* __restrict__ h_in,
                                 float* __restrict__ h_scratch,
                                 float* __restrict__ out_state,
                                 float* __restrict__ out_output) {
    const int NN = 3 * UNITS;
    int b = blockIdx.x;
    int u = threadIdx.x;               // 512
    float xz = bias[u], xr = bias[UNITS + u], xh = bias[2 * UNITS + u];
    float hz = bias[NN + u], hr = bias[NN + UNITS + u], hh = bias[NN + 2 * UNITS + u];
#pragma unroll
    for (int z = 0; z < 8; z++) {
        const float* px = part + (size_t)z * BATCH * NN + b * NN;
        const float* ph = part + (size_t)(8 + z) * BATCH * NN + b * NN;
        xz += px[u]; xr += px[UNITS + u]; xh += px[2 * UNITS + u];
        hz += ph[u]; hr += ph[UNITS + u]; hh += ph[2 * UNITS + u];
    }
    float z = 1.f / (1.f + expf(-(xz + hz)));
    float r = 1.f / (1.f + expf(-(xr + hr)));
    float hc = tanhf(xh + r * hh);
    float h = h_in[b * UNITS + u];
    float hn = z * h + (1.f - z) * hc;
    h_scratch[b * UNITS + u] = hn;
    if (out_state)  out_state[b * UNITS + u] = hn;
    if (out_output) out_output[b * UNITS + u] = hn;
}

// ---------------- attention score, 4 batch rows per block (R6-proven) -----------
__global__ void attn_score_kernel(const float* __restrict__ vproj,
                                  const float* __restrict__ qproj,
                                  const float* __restrict__ Vw,
                                  const float* __restrict__ Vb,
                                  float* __restrict__ score) {
    __shared__ float q_s[4][UNITS];
    __shared__ float vw_s[UNITS];
    __shared__ float v_s[128][33];
    const int tid = threadIdx.x;       // 128
    const int p0 = blockIdx.x * 128;
    const int b0 = blockIdx.y * 4;

    for (int t = tid; t < 4 * UNITS; t += 128) {
        int b = t >> 9, u = t & 511;
        q_s[b][u] = qproj[(b0 + b) * UNITS + u];
    }
    for (int t = tid; t < UNITS; t += 128) vw_s[t] = Vw[t];

    float acc0 = 0.f, acc1 = 0.f, acc2 = 0.f, acc3 = 0.f;
    for (int u0 = 0; u0 < UNITS; u0 += 32) {
        __syncthreads();
        for (int t = tid; t < 128 * 32; t += 128) {
            int p = t >> 5, j = t & 31;
            v_s[p][j] = (p0 + p < POI) ? vproj[(p0 + p) * UNITS + u0 + j] : 0.f;
        }
        __syncthreads();
#pragma unroll
        for (int j = 0; j < 32; ++j) {
            float v  = v_s[tid][j];
            float vw = vw_s[u0 + j];
            acc0 = fmaf(vw, tanh_ap(v + q_s[0][u0 + j]), acc0);
            acc1 = fmaf(vw, tanh_ap(v + q_s[1][u0 + j]), acc1);
            acc2 = fmaf(vw, tanh_ap(v + q_s[2][u0 + j]), acc2);
            acc3 = fmaf(vw, tanh_ap(v + q_s[3][u0 + j]), acc3);
        }
    }
    if (p0 + tid < POI) {
        float vb = Vb[0];
        score[(b0 + 0) * POI + p0 + tid] = acc0 + vb;
        score[(b0 + 1) * POI + p0 + tid] = acc1 + vb;
        score[(b0 + 2) * POI + p0 + tid] = acc2 + vb;
        score[(b0 + 3) * POI + p0 + tid] = acc3 + vb;
    }
}

// ---------------- softmax over POI per batch row (in place) ----------------
__global__ void softmax_rows_kernel(float* __restrict__ score) {
    int b = blockIdx.x;
    int tid = threadIdx.x;             // 256
    __shared__ float red[256];
    float m = -1e30f;
    for (int p = tid; p < POI; p += 256) m = fmaxf(m, score[b * POI + p]);
    red[tid] = m;
    __syncthreads();
    for (int s = 128; s > 0; s >>= 1) {
        if (tid < s) red[tid] = fmaxf(red[tid], red[tid + s]);
        __syncthreads();
    }
    m = red[0];
    __syncthreads();
    float sum = 0.f;
    for (int p = tid; p < POI; p += 256) {
        float e = __expf(score[b * POI + p] - m);
        score[b * POI + p] = e;
        sum += e;
    }
    red[tid] = sum;
    __syncthreads();
    for (int s = 128; s > 0; s >>= 1) {
        if (tid < s) red[tid] += red[tid + s];
        __syncthreads();
    }
    float inv = 1.f / red[0];
    for (int p = tid; p < POI; p += 256) score[b * POI + p] *= inv;
}

// ---------------- context partials: 4 batch rows per block, NCH p-chunks --------
__global__ void context_partial_kernel(const float* __restrict__ attn,
                                       const float* __restrict__ emb,
                                       float* __restrict__ part) {
    const int PC = POI / NCH;          // 500
    int b0 = blockIdx.x * 4;
    int ch = blockIdx.y;
    int e  = threadIdx.x;              // 256 == EMB
    int p0 = ch * PC;
    const float* a0 = attn + (b0 + 0) * POI;
    const float* a1 = attn + (b0 + 1) * POI;
    const float* a2 = attn + (b0 + 2) * POI;
    const float* a3 = attn + (b0 + 3) * POI;
    float c0 = 0.f, c1 = 0.f, c2 = 0.f, c3 = 0.f;
#pragma unroll 4
    for (int p = p0; p < p0 + PC; ++p) {
        float ev = emb[p * EMB + e];
        c0 = fmaf(a0[p], ev, c0);
        c1 = fmaf(a1[p], ev, c1);
        c2 = fmaf(a2[p], ev, c2);
        c3 = fmaf(a3[p], ev, c3);
    }
    part[(ch * BATCH + b0 + 0) * EMB + e] = c0;
    part[(ch * BATCH + b0 + 1) * EMB + e] = c1;
    part[(ch * BATCH + b0 + 2) * EMB + e] = c2;
    part[(ch * BATCH + b0 + 3) * EMB + e] = c3;
}

// ---------------- outcat = [sum(ctx partials) | h | cat_dec] ----------------
__global__ void build_outcat_kernel(const float* __restrict__ part,
                                    const float* __restrict__ h,
                                    const float* __restrict__ cat_dec,
                                    float* __restrict__ outcat) {
    int b = blockIdx.x;
    int e = threadIdx.x;               // 256
    float s = 0.f;
#pragma unroll
    for (int ch = 0; ch < NCH; ch++) s += part[(ch * BATCH + b) * EMB + e];
    outcat[b * CATDIM + e] = s;
    for (int c = e; c < UNITS; c += 256) {
        outcat[b * CATDIM + EMB + c]         = h[b * UNITS + c];
        outcat[b * CATDIM + EMB + UNITS + c] = cat_dec[b * UNITS + c];
    }
}

// ---------------- launch ----------------
extern "C" void kernel_launch(void* const* d_in, const int* in_sizes, int n_in,
                              void* d_out, int out_size) {
    const int*   x          = (const int*)  d_in[0];
    const float* query      = (const float*)d_in[1];
    const float* emb        = (const float*)d_in[2];
    // d_in[3] = A_hat (unused)
    const float* dec_hidden = (const float*)d_in[4];
    const float* cat_dec    = (const float*)d_in[5];
    const float* gru_kernel = (const float*)d_in[6];
    const float* gru_rec    = (const float*)d_in[7];
    const float* gru_bias   = (const float*)d_in[8];
    const float* W1_w       = (const float*)d_in[9];
    const float* W1_b       = (const float*)d_in[10];
    const float* W2_w       = (const float*)d_in[11];
    const float* W2_b       = (const float*)d_in[12];
    const float* V_w        = (const float*)d_in[13];
    const float* V_b        = (const float*)d_in[14];
    const float* fc_w       = (const float*)d_in[15];
    const float* fc_b       = (const float*)d_in[16];

    float* out        = (float*)d_out;
    float* out_logits = out;
    float* out_state  = (out_size >= BATCH * POI + BATCH * UNITS)
                        ? out + BATCH * POI : nullptr;
    float* out_output = (out_size >= BATCH * POI + 2 * BATCH * UNITS)
                        ? out + BATCH * POI + BATCH * UNITS : nullptr;

    float *g_h_p, *g_qp_p, *g_vp_p, *g_sc_p, *g_cp_p, *g_oc_p, *g_pt_p;
    cudaGetSymbolAddress((void**)&g_h_p,  g_h);
    cudaGetSymbolAddress((void**)&g_qp_p, g_qproj);
    cudaGetSymbolAddress((void**)&g_vp_p, g_vproj);
    cudaGetSymbolAddress((void**)&g_sc_p, g_score);
    cudaGetSymbolAddress((void**)&g_cp_p, g_ctxpart);
    cudaGetSymbolAddress((void**)&g_oc_p, g_outcat);
    cudaGetSymbolAddress((void**)&g_pt_p, g_part);

    // One-time stream/event setup (first call is the uncaptured correctness run;
    // later captured calls reuse them — same launch sequence every call).
    static cudaStream_t s2 = nullptr;
    static cudaEvent_t evFork = nullptr, evJoin = nullptr;
    if (!s2) {
        cudaStreamCreateWithFlags(&s2, cudaStreamNonBlocking);
        cudaEventCreateWithFlags(&evFork, cudaEventDisableTiming);
        cudaEventCreateWithFlags(&evJoin, cudaEventDisableTiming);
    }

    // ---- fork: vproj (independent) runs on s2, overlapping the GRU chain ----
    cudaEventRecord(evFork, 0);
    cudaStreamWaitEvent(s2, evFork, 0);

    // v_proj = emb @ W1 + b : 128x64 tiles (R6-proven shape), on s2
    gemm_v2_kernel<128, 64, 8, 4><<<dim3(UNITS / 64, (POI + 127) / 128, 1), 256, 0, s2>>>(
        emb, W1_w, W1_b, g_vp_p, POI, UNITS, EMB, EMB);
    cudaEventRecord(evJoin, s2);

    // ---- GRU chain on main stream (concurrent with vproj) ----
    gru_mm_kernel<<<dim3(3 * UNITS / 64, 1, 16), 256>>>(
        x, query, emb, dec_hidden, gru_kernel, gru_rec, g_pt_p);
    gru_gates_kernel<<<BATCH, UNITS>>>(g_pt_p, gru_bias, dec_hidden,
                                       g_h_p, out_state, out_output);
    gemm_v2_kernel<64, 64, 4, 4><<<dim3(UNITS / 64, 1, 8), 256>>>(
        g_h_p, W2_w, nullptr, g_pt_p, BATCH, UNITS, UNITS, 64);
    reduce_bias_kernel<<<(BATCH * UNITS + 255) / 256, 256>>>(
        g_pt_p, W2_b, g_qp_p, BATCH * UNITS, UNITS, 8);

    // ---- join: attention needs vproj ----
    cudaStreamWaitEvent(0, evJoin, 0);

    attn_score_kernel<<<dim3((POI + 127) / 128, BATCH / 4), 128>>>(
        g_vp_p, g_qp_p, V_w, V_b, g_sc_p);
    softmax_rows_kernel<<<BATCH, 256>>>(g_sc_p);
    context_partial_kernel<<<dim3(BATCH / 4, NCH), 256>>>(g_sc_p, emb, g_cp_p);
    build_outcat_kernel<<<BATCH, 256>>>(g_cp_p, g_h_p, cat_dec, g_oc_p);

    // logits = outcat @ fc_w + fc_b : split 10
    gemm_v2_kernel<64, 128, 4, 8><<<dim3((POI + 127) / 128, 1, 10), 256>>>(
        g_oc_p, fc_w, nullptr, g_pt_p, BATCH, POI, CATDIM, 128);
    reduce_bias_kernel<<<(BATCH * POI + 255) / 256, 256>>>(
        g_pt_p, fc_b, out_logits, BATCH * POI, POI, 10);
}